// round 15
// baseline (speedup 1.0000x reference)
#include <cuda_runtime.h>
#include <cstdint>

#define M_DIM 32
#define K_DIM 16384
#define N_DIM 16384
#define KCH 16                       // k rows per staged chunk
#define KSPL 9                       // K splits (576 CTAs = 97% of 592 slots)
#define NB_TILE 256
#define PADX 34                      // x row pitch in floats (136B: 8B-aligned)

typedef unsigned long long ull;

// Static scratch (no allocation allowed)
__device__ float g_xT[K_DIM * M_DIM];            // 2 MB, xT[k][m] = relu(img)/128

__device__ __forceinline__ ull add2(ull a, ull b) {
    ull d;
    asm("add.rn.f32x2 %0, %1, %2;" : "=l"(d) : "l"(a), "l"(b));
    return d;
}
__device__ __forceinline__ void cp_async16(void* s, const void* g) {
    unsigned sa = (unsigned)__cvta_generic_to_shared(s);
    asm volatile("cp.async.cg.shared.global [%0], [%1], 16;" :: "r"(sa), "l"(g));
}
__device__ __forceinline__ void cp_async8(void* s, const void* g) {
    unsigned sa = (unsigned)__cvta_generic_to_shared(s);
    asm volatile("cp.async.ca.shared.global [%0], [%1], 8;" :: "r"(sa), "l"(g));
}

// ---------- kernel 1: transpose x (relu + /128) AND zero the poisoned out ----
// 128 CTAs x 256 threads; CTA transposes a 128k x 32m tile. Scalar smem ops
// only (no vector STS/LDS -> no alignment hazard), conflict-free both phases.
__global__ __launch_bounds__(256)
void prep_xt_kernel(const float* __restrict__ img, float4* __restrict__ out) {
    __shared__ float s[128][33];                     // k-major, pad 33
    const int kb  = blockIdx.x;                      // 128 tiles
    const int tid = threadIdx.x;
    const int k0  = kb * 128;

    // zero 4096 floats (1024 float4) of out per CTA: 128*4096 = 524288 total
    {
        float4 z = make_float4(0.f, 0.f, 0.f, 0.f);
        #pragma unroll
        for (int p = 0; p < 4; ++p)
            out[(size_t)kb * 1024 + tid + p * 256] = z;
    }

    // load phase: 32 m-rows x 128 k (16 KB), 4 independent LDG.128 per thread;
    // scatter each float4 as 4 scalar STS into k-major smem (conflict-free).
    #pragma unroll
    for (int p = 0; p < 4; ++p) {
        int i = tid + p * 256;          // 0..1023 float4
        int m = i >> 5, c4 = i & 31;    // m-row, float4-in-row
        float4 v = *(const float4*)(img + (size_t)m * K_DIM + k0 + c4 * 4);
        s[c4 * 4 + 0][m] = v.x;
        s[c4 * 4 + 1][m] = v.y;
        s[c4 * 4 + 2][m] = v.z;
        s[c4 * 4 + 3][m] = v.w;
    }
    __syncthreads();

    // store phase: 128 k-rows x 32 m; gather 4 scalar LDS (conflict-free),
    // fuse relu + /128, STG.128 coalesced.
    #pragma unroll
    for (int p = 0; p < 4; ++p) {
        int i = tid + p * 256;          // 0..1023 float4
        int kk = i >> 3, q = i & 7;
        float4 v;
        v.x = fmaxf(s[kk][4 * q + 0], 0.f) * (1.0f / 128.0f);
        v.y = fmaxf(s[kk][4 * q + 1], 0.f) * (1.0f / 128.0f);
        v.z = fmaxf(s[kk][4 * q + 2], 0.f) * (1.0f / 128.0f);
        v.w = fmaxf(s[kk][4 * q + 3], 0.f) * (1.0f / 128.0f);
        *(float4*)(g_xT + (size_t)(k0 + kk) * M_DIM + q * 4) = v;
    }
}

// ---------- kernel 2: fused, cp.async double-buffered stream + ffs accumulate --
// grid (64 n-tiles, 9 k-splits) = 576 CTAs, 256 threads; thread owns one n, 32 m.
// 1024 chunks per n-tile split 7x114 + 2x113 across the 9 kb's.
__global__ __launch_bounds__(256, 4)
void spmm_fused(const float* __restrict__ V, float* __restrict__ out) {
    __shared__ __align__(16) float sv[2][KCH * NB_TILE];  // 2 x 16 KB
    __shared__ __align__(16) float sx[2][KCH * PADX];     // 2 x 2.2 KB

    const int nb = blockIdx.x, kb = blockIdx.y;
    const int tid = threadIdx.x;
    const int nloc = tid;                 // thread owns column nloc (0..255)
    const int n = nb * NB_TILE + nloc;

    // chunk range: first 7 splits get 114 chunks, last 2 get 113
    const int start = kb * 113 + (kb < 7 ? kb : 7);
    const int count = 113 + (kb < 7 ? 1 : 0);

    ull acc[16];
    #pragma unroll
    for (int q = 0; q < 16; ++q) acc[q] = 0ull;

#define PREFETCH(gg, bb)                                                       \
    {                                                                          \
        const int pk0 = (gg) * KCH;                                            \
        _Pragma("unroll")                                                      \
        for (int p = 0; p < 4; ++p) {          /* 16KB V chunk */              \
            int i = tid + p * 256;             /* 0..1023 float4 */            \
            int kk = i >> 6, q = i & 63;                                       \
            cp_async16(&sv[bb][kk * NB_TILE + q * 4],                          \
                       V + (size_t)(pk0 + kk) * N_DIM + nb * NB_TILE + q * 4); \
        }                                                                      \
        {                                      /* 2KB x chunk, padded rows */  \
            int kk = tid >> 4, q = tid & 15;                                   \
            cp_async8(&sx[bb][kk * PADX + q * 2],                              \
                      g_xT + (size_t)(pk0 + kk) * M_DIM + q * 2);              \
        }                                                                      \
    }

    PREFETCH(start, 0)
    asm volatile("cp.async.commit_group;");

    for (int c = 0; c < count; ++c) {
        const int buf = c & 1;
        if (c + 1 < count) PREFETCH(start + c + 1, (c + 1) & 1)
        asm volatile("cp.async.commit_group;");   // uniform group count
        asm volatile("cp.async.wait_group 1;");   // chunk c landed
        __syncthreads();

        // build this thread's 16-bit k-word from its n column (conflict-free LDS)
        unsigned x = 0;
        const float* col = &sv[buf][nloc];
        #pragma unroll
        for (int j = 0; j < KCH; ++j) {
            if (col[j * NB_TILE] != 0.0f) x |= (1u << j);
        }
        // lane-private sparse walk
        while (x) {
            int j = __ffs(x) - 1;
            x &= x - 1;
            const ull* xr = (const ull*)(&sx[buf][j * PADX]);
            #pragma unroll
            for (int q = 0; q < 16; ++q) acc[q] = add2(acc[q], xr[q]);
        }
        __syncthreads();   // buf consumed; safe to overwrite next iteration
    }
#undef PREFETCH

    // epilogue: combine split-K in place via no-return global reductions
    #pragma unroll
    for (int q = 0; q < 16; ++q) {
        float lo = __uint_as_float((unsigned)(acc[q] & 0xffffffffull));
        float hi = __uint_as_float((unsigned)(acc[q] >> 32));
        atomicAdd(&out[(size_t)(2 * q) * N_DIM + n], lo);
        atomicAdd(&out[(size_t)(2 * q + 1) * N_DIM + n], hi);
    }
}

extern "C" void kernel_launch(void* const* d_in, const int* in_sizes, int n_in,
                              void* d_out, int out_size) {
    const float* img = (const float*)d_in[0];   // (2,16,128,128)
    const float* V   = (const float*)d_in[1];   // (128,128,128,128)
    float* out = (float*)d_out;

    (void)in_sizes; (void)n_in; (void)out_size;

    prep_xt_kernel<<<K_DIM / 128, 256>>>(img, (float4*)out);

    dim3 grid(N_DIM / NB_TILE, KSPL);   // (64, 9) = 576 CTAs
    spmm_fused<<<grid, 256>>>(V, out);
}

// round 16
// speedup vs baseline: 1.0097x; 1.0097x over previous
#include <cuda_runtime.h>
#include <cstdint>

#define M_DIM 32
#define K_DIM 16384
#define N_DIM 16384
#define KCH 16                       // k rows per staged chunk
#define KSPL 9                       // K splits (576 CTAs = 97% of 592 slots)
#define NB_TILE 256
#define PADX 34                      // x row pitch in floats (136B: 8B-aligned)

typedef unsigned long long ull;

// Static scratch (no allocation allowed)
__device__ float g_xT[K_DIM * M_DIM];            // 2 MB, xT[k][m] = relu(img)/128

__device__ __forceinline__ ull add2(ull a, ull b) {
    ull d;
    asm("add.rn.f32x2 %0, %1, %2;" : "=l"(d) : "l"(a), "l"(b));
    return d;
}
__device__ __forceinline__ void cp_async16(void* s, const void* g) {
    unsigned sa = (unsigned)__cvta_generic_to_shared(s);
    asm volatile("cp.async.cg.shared.global [%0], [%1], 16;" :: "r"(sa), "l"(g));
}
__device__ __forceinline__ void cp_async8(void* s, const void* g) {
    unsigned sa = (unsigned)__cvta_generic_to_shared(s);
    asm volatile("cp.async.ca.shared.global [%0], [%1], 8;" :: "r"(sa), "l"(g));
}

// ---------- kernel 1: transpose x (relu + /128) AND zero the poisoned out ----
// 128 CTAs x 256 threads; CTA transposes a 128k x 32m tile. Scalar smem ops
// only, conflict-free both phases. Triggers PDL completion at the end.
__global__ __launch_bounds__(256)
void prep_xt_kernel(const float* __restrict__ img, float4* __restrict__ out) {
    __shared__ float s[128][33];                     // k-major, pad 33
    const int kb  = blockIdx.x;                      // 128 tiles
    const int tid = threadIdx.x;
    const int k0  = kb * 128;

    // zero 4096 floats (1024 float4) of out per CTA: 128*4096 = 524288 total
    {
        float4 z = make_float4(0.f, 0.f, 0.f, 0.f);
        #pragma unroll
        for (int p = 0; p < 4; ++p)
            out[(size_t)kb * 1024 + tid + p * 256] = z;
    }

    // load phase: 32 m-rows x 128 k (16 KB), 4 independent LDG.128 per thread;
    // scatter each float4 as 4 scalar STS into k-major smem (conflict-free).
    #pragma unroll
    for (int p = 0; p < 4; ++p) {
        int i = tid + p * 256;          // 0..1023 float4
        int m = i >> 5, c4 = i & 31;    // m-row, float4-in-row
        float4 v = *(const float4*)(img + (size_t)m * K_DIM + k0 + c4 * 4);
        s[c4 * 4 + 0][m] = v.x;
        s[c4 * 4 + 1][m] = v.y;
        s[c4 * 4 + 2][m] = v.z;
        s[c4 * 4 + 3][m] = v.w;
    }
    __syncthreads();

    // store phase: 128 k-rows x 32 m; gather 4 scalar LDS (conflict-free),
    // fuse relu + /128, STG.128 coalesced.
    #pragma unroll
    for (int p = 0; p < 4; ++p) {
        int i = tid + p * 256;          // 0..1023 float4
        int kk = i >> 3, q = i & 7;
        float4 v;
        v.x = fmaxf(s[kk][4 * q + 0], 0.f) * (1.0f / 128.0f);
        v.y = fmaxf(s[kk][4 * q + 1], 0.f) * (1.0f / 128.0f);
        v.z = fmaxf(s[kk][4 * q + 2], 0.f) * (1.0f / 128.0f);
        v.w = fmaxf(s[kk][4 * q + 3], 0.f) * (1.0f / 128.0f);
        *(float4*)(g_xT + (size_t)(k0 + kk) * M_DIM + q * 4) = v;
    }

    // let the dependent spmm grid launch; its griddepcontrol.wait orders
    // these stores before any consumer load.
    cudaTriggerProgrammaticLaunchCompletion();
}

// ---------- kernel 2: fused, cp.async double-buffered stream + ffs accumulate --
// grid (64 n-tiles, 9 k-splits) = 576 CTAs, 256 threads; thread owns one n, 32 m.
// 1024 chunks per n-tile split 7x114 + 2x113 across the 9 kb's.
__global__ __launch_bounds__(256, 4)
void spmm_fused(const float* __restrict__ V, float* __restrict__ out) {
    __shared__ __align__(16) float sv[2][KCH * NB_TILE];  // 2 x 16 KB
    __shared__ __align__(16) float sx[2][KCH * PADX];     // 2 x 2.2 KB

    // PDL: wait for prep's stores (g_xT and the zeroed out) to be visible.
    cudaGridDependencySynchronize();

    const int nb = blockIdx.x, kb = blockIdx.y;
    const int tid = threadIdx.x;
    const int nloc = tid;                 // thread owns column nloc (0..255)
    const int n = nb * NB_TILE + nloc;

    // chunk range: first 7 splits get 114 chunks, last 2 get 113
    const int start = kb * 113 + (kb < 7 ? kb : 7);
    const int count = 113 + (kb < 7 ? 1 : 0);

    ull acc[16];
    #pragma unroll
    for (int q = 0; q < 16; ++q) acc[q] = 0ull;

#define PREFETCH(gg, bb)                                                       \
    {                                                                          \
        const int pk0 = (gg) * KCH;                                            \
        _Pragma("unroll")                                                      \
        for (int p = 0; p < 4; ++p) {          /* 16KB V chunk */              \
            int i = tid + p * 256;             /* 0..1023 float4 */            \
            int kk = i >> 6, q = i & 63;                                       \
            cp_async16(&sv[bb][kk * NB_TILE + q * 4],                          \
                       V + (size_t)(pk0 + kk) * N_DIM + nb * NB_TILE + q * 4); \
        }                                                                      \
        {                                      /* 2KB x chunk, padded rows */  \
            int kk = tid >> 4, q = tid & 15;                                   \
            cp_async8(&sx[bb][kk * PADX + q * 2],                              \
                      g_xT + (size_t)(pk0 + kk) * M_DIM + q * 2);              \
        }                                                                      \
    }

    PREFETCH(start, 0)
    asm volatile("cp.async.commit_group;");

    for (int c = 0; c < count; ++c) {
        const int buf = c & 1;
        if (c + 1 < count) PREFETCH(start + c + 1, (c + 1) & 1)
        asm volatile("cp.async.commit_group;");   // uniform group count
        asm volatile("cp.async.wait_group 1;");   // chunk c landed
        __syncthreads();

        // build this thread's 16-bit k-word from its n column (conflict-free LDS)
        unsigned x = 0;
        const float* col = &sv[buf][nloc];
        #pragma unroll
        for (int j = 0; j < KCH; ++j) {
            if (col[j * NB_TILE] != 0.0f) x |= (1u << j);
        }
        // lane-private sparse walk
        while (x) {
            int j = __ffs(x) - 1;
            x &= x - 1;
            const ull* xr = (const ull*)(&sx[buf][j * PADX]);
            #pragma unroll
            for (int q = 0; q < 16; ++q) acc[q] = add2(acc[q], xr[q]);
        }
        __syncthreads();   // buf consumed; safe to overwrite next iteration
    }
#undef PREFETCH

    // epilogue: combine split-K in place via no-return global reductions
    #pragma unroll
    for (int q = 0; q < 16; ++q) {
        float lo = __uint_as_float((unsigned)(acc[q] & 0xffffffffull));
        float hi = __uint_as_float((unsigned)(acc[q] >> 32));
        atomicAdd(&out[(size_t)(2 * q) * N_DIM + n], lo);
        atomicAdd(&out[(size_t)(2 * q + 1) * N_DIM + n], hi);
    }
}

extern "C" void kernel_launch(void* const* d_in, const int* in_sizes, int n_in,
                              void* d_out, int out_size) {
    const float* img = (const float*)d_in[0];   // (2,16,128,128)
    const float* V   = (const float*)d_in[1];   // (128,128,128,128)
    float* out = (float*)d_out;

    (void)in_sizes; (void)n_in; (void)out_size;

    prep_xt_kernel<<<K_DIM / 128, 256>>>(img, (float4*)out);

    // spmm launched as a programmatic dependent of prep: its launch overhead
    // and prologue overlap prep's tail; griddepcontrol.wait provides ordering.
    cudaLaunchConfig_t cfg = {};
    cfg.gridDim  = dim3(N_DIM / NB_TILE, KSPL);   // (64, 9) = 576 CTAs
    cfg.blockDim = dim3(256, 1, 1);
    cfg.dynamicSmemBytes = 0;
    cfg.stream = 0;
    cudaLaunchAttribute attrs[1];
    attrs[0].id = cudaLaunchAttributeProgrammaticStreamSerialization;
    attrs[0].val.programmaticStreamSerializationAllowed = 1;
    cfg.attrs = attrs;
    cfg.numAttrs = 1;
    cudaLaunchKernelEx(&cfg, spmm_fused, V, out);
}